// round 4
// baseline (speedup 1.0000x reference)
#include <cuda_runtime.h>

#define BB 16
#define NN 16384
#define GG 128
#define NS 256
#define NFG 64

// Scratch (no allocations allowed) — ~3MB of __device__ globals.
__device__ int   g_label[BB*NN];
__device__ int   g_argmax[BB*NN];
__device__ float g_r[BB*NN];

// ---------------------------------------------------------------------------
// JAX threefry2x32 with key = jax.random.key(1) -> (k0,k1) = (0,1)
// ---------------------------------------------------------------------------
__device__ __forceinline__ uint2 threefry2x32(unsigned x0, unsigned x1) {
  const unsigned ks0 = 0u, ks1 = 1u, ks2 = 0x1BD11BDBu; // 0^1^0x1BD11BDA
  unsigned ks[3] = {ks0, ks1, ks2};
  x0 += ks[0]; x1 += ks[1];
  const int R0[4] = {13, 15, 26, 6};
  const int R1[4] = {17, 29, 16, 24};
#pragma unroll
  for (int i = 0; i < 5; ++i) {
#pragma unroll
    for (int j = 0; j < 4; ++j) {
      int r = (i & 1) ? R1[j] : R0[j];
      x0 += x1;
      x1 = (x1 << r) | (x1 >> (32 - r));
      x1 ^= x0;
    }
    x0 += ks[(i + 1) % 3];
    x1 += ks[(i + 2) % 3] + (unsigned)(i + 1);
  }
  return make_uint2(x0, x1);
}

// Partitionable path (JAX >= 0.5 default): per-element 64-bit counter,
// x = (hi32(i), lo32(i)) = (0, i); 32-bit output = out.x ^ out.y
__device__ __forceinline__ unsigned jax_bits(unsigned i) {
  uint2 o = threefry2x32(0u, i);
  return o.x ^ o.y;
}

// ---------------------------------------------------------------------------
// Stage 1: per-proposal max IoU / argmax / label / r   (bit-exact float ops)
// ---------------------------------------------------------------------------
__global__ void ptl_stage1(const float* __restrict__ prop, const float* __restrict__ gt) {
  __shared__ float4 sgt[GG];
  const int b = blockIdx.y;
  const int n = blockIdx.x * blockDim.x + threadIdx.x;
  for (int i = threadIdx.x; i < GG; i += blockDim.x)
    sgt[i] = reinterpret_cast<const float4*>(gt)[b * GG + i];
  __syncthreads();

  float4 p = reinterpret_cast<const float4*>(prop)[b * NN + n];
  float ap = __fmul_rn(__fsub_rn(p.z, p.x), __fsub_rn(p.w, p.y));
  float best = -1.0f;
  int bi = 0;
#pragma unroll 4
  for (int g = 0; g < GG; ++g) {
    float4 q = sgt[g];
    float ix1 = fmaxf(p.x, q.x);
    float iy1 = fmaxf(p.y, q.y);
    float ix2 = fminf(p.z, q.z);
    float iy2 = fminf(p.w, q.w);
    float iw = fmaxf(__fsub_rn(ix2, ix1), 0.0f);
    float ih = fmaxf(__fsub_rn(iy2, iy1), 0.0f);
    float inter = __fmul_rn(iw, ih);
    float ag = __fmul_rn(__fsub_rn(q.z, q.x), __fsub_rn(q.w, q.y));
    float den = fmaxf(__fsub_rn(__fadd_rn(ap, ag), inter), 1e-8f);
    float iou = __fdiv_rn(inter, den);
    if (iou > best) { best = iou; bi = g; }   // first-max == jnp.argmax
  }
  int lab = (best >= 0.5f) ? 1 : ((best < 0.1f) ? 0 : -1);

  const int i = b * NN + n;
  unsigned bits = jax_bits((unsigned)i);
  float u = __fsub_rn(__uint_as_float((bits >> 9) | 0x3F800000u), 1.0f);

  g_label[i]  = lab;
  g_argmax[i] = bi;
  g_r[i]      = u;
}

// ---------------------------------------------------------------------------
// Stage 2: one CTA per batch — exact selection via 64-bit radix select
// key = (float_bits << 32) | (16383 - n)  -> (value desc, index asc), distinct
// ---------------------------------------------------------------------------
__global__ void __launch_bounds__(1024) ptl_stage2(const float* __restrict__ prop,
                                                   const float* __restrict__ gt,
                                                   float* __restrict__ out) {
  __shared__ unsigned hist[256];
  __shared__ unsigned long long s_prefix;
  __shared__ int s_target;
  __shared__ int s_npos;
  __shared__ int s_cnt;
  __shared__ unsigned long long cand[NS];

  const int b = blockIdx.x;
  const int tid = threadIdx.x;
  const int*   lab = g_label + b * NN;
  const float* rr  = g_r + b * NN;

  // ---- count positives ----
  if (tid == 0) s_npos = 0;
  __syncthreads();
  {
    int c = 0;
    for (int n = tid; n < NN; n += 1024) c += (__ldg(&lab[n]) == 1);
    for (int o = 16; o; o >>= 1) c += __shfl_down_sync(0xffffffffu, c, o);
    if ((tid & 31) == 0) atomicAdd(&s_npos, c);
  }
  __syncthreads();
  const int npos = s_npos;

  // ---- Phase A: threshold for top-64 positives by (r desc, idx asc) ----
  unsigned long long threshA = 0ull;
  if (npos > NFG) {
    if (tid == 0) { s_prefix = 0ull; s_target = NFG; }
    __syncthreads();
    for (int byte = 7; byte >= 0; --byte) {
      for (int i = tid; i < 256; i += 1024) hist[i] = 0;
      __syncthreads();
      unsigned long long pfx = s_prefix;
      for (int n = tid; n < NN; n += 1024) {
        int bv = -1;
        if (__ldg(&lab[n]) == 1) {
          unsigned long long k =
              ((unsigned long long)__float_as_uint(__ldg(&rr[n])) << 32) | (unsigned)(NN - 1 - n);
          bool ok = (byte == 7) || ((k >> ((byte + 1) * 8)) == (pfx >> ((byte + 1) * 8)));
          if (ok) bv = (int)((k >> (byte * 8)) & 0xFFull);
        }
        unsigned m = __match_any_sync(0xffffffffu, bv);
        if (bv >= 0 && (tid & 31) == (__ffs(m) - 1)) atomicAdd(&hist[bv], (unsigned)__popc(m));
      }
      __syncthreads();
      if (tid == 0) {
        int cum = 0, tgt = s_target;
        for (int v = 255; v >= 0; --v) {
          int c = (int)hist[v];
          if (cum + c >= tgt) { s_prefix |= ((unsigned long long)v) << (byte * 8); s_target = tgt - cum; break; }
          cum += c;
        }
      }
      __syncthreads();
    }
    threshA = s_prefix;
  }
  __syncthreads();

  // ---- Phase B: threshold for top-256 by prio = cat + r (float32) ----
  if (tid == 0) { s_prefix = 0ull; s_target = NS; }
  __syncthreads();
  for (int byte = 7; byte >= 0; --byte) {
    for (int i = tid; i < 256; i += 1024) hist[i] = 0;
    __syncthreads();
    unsigned long long pfx = s_prefix;
    for (int n = tid; n < NN; n += 1024) {
      int l = __ldg(&lab[n]);
      float rv = __ldg(&rr[n]);
      unsigned rb = __float_as_uint(rv);
      float cat;
      if (l == 1) {
        unsigned long long ka = ((unsigned long long)rb << 32) | (unsigned)(NN - 1 - n);
        cat = (ka >= threshA) ? 3.0f : 1.0f;
      } else {
        cat = (l == 0) ? 2.0f : 0.0f;
      }
      unsigned long long k =
          ((unsigned long long)__float_as_uint(__fadd_rn(cat, rv)) << 32) | (unsigned)(NN - 1 - n);
      bool ok = (byte == 7) || ((k >> ((byte + 1) * 8)) == (pfx >> ((byte + 1) * 8)));
      int bv = ok ? (int)((k >> (byte * 8)) & 0xFFull) : -1;
      unsigned m = __match_any_sync(0xffffffffu, bv);
      if (bv >= 0 && (tid & 31) == (__ffs(m) - 1)) atomicAdd(&hist[bv], (unsigned)__popc(m));
    }
    __syncthreads();
    if (tid == 0) {
      int cum = 0, tgt = s_target;
      for (int v = 255; v >= 0; --v) {
        int c = (int)hist[v];
        if (cum + c >= tgt) { s_prefix |= ((unsigned long long)v) << (byte * 8); s_target = tgt - cum; break; }
        cum += c;
      }
    }
    __syncthreads();
  }
  const unsigned long long threshB = s_prefix;

  // ---- compact the exactly-256 winners ----
  if (tid == 0) s_cnt = 0;
  if (tid < NS) cand[tid] = 0ull;
  __syncthreads();
  for (int n = tid; n < NN; n += 1024) {
    int l = __ldg(&lab[n]);
    float rv = __ldg(&rr[n]);
    unsigned rb = __float_as_uint(rv);
    float cat;
    if (l == 1) {
      unsigned long long ka = ((unsigned long long)rb << 32) | (unsigned)(NN - 1 - n);
      cat = (ka >= threshA) ? 3.0f : 1.0f;
    } else {
      cat = (l == 0) ? 2.0f : 0.0f;
    }
    unsigned long long k =
        ((unsigned long long)__float_as_uint(__fadd_rn(cat, rv)) << 32) | (unsigned)(NN - 1 - n);
    if (k >= threshB) {
      int s = atomicAdd(&s_cnt, 1);
      if (s < NS) cand[s] = k;
    }
  }
  __syncthreads();

  // ---- bitonic sort 256 keys descending (= lax.top_k order incl. ties) ----
  for (int kk = 2; kk <= NS; kk <<= 1) {
    for (int j = kk >> 1; j > 0; j >>= 1) {
      if (tid < NS) {
        int i = tid, l2 = i ^ j;
        if (l2 > i) {
          unsigned long long a = cand[i], c2 = cand[l2];
          bool descBlock = ((i & kk) == 0);
          if (descBlock ? (a < c2) : (a > c2)) { cand[i] = c2; cand[l2] = a; }
        }
      }
      __syncthreads();
    }
  }

  // ---- outputs ----
  if (tid < NS) {
    const int s = tid;
    unsigned long long k = cand[s];
    int n = (NN - 1) - (int)(unsigned)(k & 0xFFFFFFFFull);
    int l = lab[n];
    int bl = (l == 1) ? 1 : 0;                 // max(label, 0)
    float4 p = reinterpret_cast<const float4*>(prop)[b * NN + n];
    int gi = g_argmax[b * NN + n];
    float4 q = reinterpret_cast<const float4*>(gt)[b * GG + gi];

    float rcx = __fmul_rn(__fadd_rn(p.x, p.z), 0.5f);
    float rcy = __fmul_rn(__fadd_rn(p.y, p.w), 0.5f);
    float rw  = __fsub_rn(p.z, p.x);
    float rh  = __fsub_rn(p.w, p.y);
    float gcx = __fmul_rn(__fadd_rn(q.x, q.z), 0.5f);
    float gcy = __fmul_rn(__fadd_rn(q.y, q.w), 0.5f);
    float gw  = __fsub_rn(q.z, q.x);
    float gh  = __fsub_rn(q.w, q.y);
    float dx = __fdiv_rn(__fsub_rn(gcx, rcx), rw);
    float dy = __fdiv_rn(__fsub_rn(gcy, rcy), rh);
    float dw = logf(__fdiv_rn(gw, rw));
    float dh = logf(__fdiv_rn(gh, rh));

    const int base = b * NS + s;
    float* roi  = out;                 // [16,256,4]
    float* labo = out + BB * NS * 4;   // [16,256]
    float* tgts = out + BB * NS * 5;   // [16,256,4]
    float* inw  = out + BB * NS * 9;   // [16,256,4]
    float* outw = out + BB * NS * 13;  // [16,256,4]

    roi[base * 4 + 0] = p.x; roi[base * 4 + 1] = p.y;
    roi[base * 4 + 2] = p.z; roi[base * 4 + 3] = p.w;
    labo[base] = (float)bl;
    tgts[base * 4 + 0] = dx; tgts[base * 4 + 1] = dy;
    tgts[base * 4 + 2] = dw; tgts[base * 4 + 3] = dh;
    float w = bl ? 1.0f : 0.0f;
    inw[base * 4 + 0] = w; inw[base * 4 + 1] = w;
    inw[base * 4 + 2] = w; inw[base * 4 + 3] = w;
    outw[base * 4 + 0] = w; outw[base * 4 + 1] = w;
    outw[base * 4 + 2] = w; outw[base * 4 + 3] = w;
  }
}

extern "C" void kernel_launch(void* const* d_in, const int* in_sizes, int n_in,
                              void* d_out, int out_size) {
  const float* prop = (const float*)d_in[0];  // (16,16384,4) f32
  const float* gt   = (const float*)d_in[1];  // (16,128,4)   f32
  float* out = (float*)d_out;                 // 69632 f32, concat of 5 outputs

  ptl_stage1<<<dim3(NN / 256, BB), 256>>>(prop, gt);
  ptl_stage2<<<BB, 1024>>>(prop, gt, out);
}

// round 7
// speedup vs baseline: 2.9194x; 2.9194x over previous
#include <cuda_runtime.h>

#define BB 16
#define NN 16384
#define GG 128
#define NS 256
#define NFG 64
#define EQCAP 256

// Scratch (no allocations allowed).
__device__ int   g_label[BB*NN];
__device__ int   g_argmax[BB*NN];
__device__ float g_r[BB*NN];

// ---------------------------------------------------------------------------
// JAX threefry2x32, key = jax.random.key(1) -> (0,1); partitionable path.
// ---------------------------------------------------------------------------
__device__ __forceinline__ uint2 threefry2x32(unsigned x0, unsigned x1) {
  const unsigned ks0 = 0u, ks1 = 1u, ks2 = 0x1BD11BDBu;
  unsigned ks[3] = {ks0, ks1, ks2};
  x0 += ks[0]; x1 += ks[1];
  const int R0[4] = {13, 15, 26, 6};
  const int R1[4] = {17, 29, 16, 24};
#pragma unroll
  for (int i = 0; i < 5; ++i) {
#pragma unroll
    for (int j = 0; j < 4; ++j) {
      int r = (i & 1) ? R1[j] : R0[j];
      x0 += x1;
      x1 = (x1 << r) | (x1 >> (32 - r));
      x1 ^= x0;
    }
    x0 += ks[(i + 1) % 3];
    x1 += ks[(i + 2) % 3] + (unsigned)(i + 1);
  }
  return make_uint2(x0, x1);
}
__device__ __forceinline__ unsigned jax_bits(unsigned i) {
  uint2 o = threefry2x32(0u, i);
  return o.x ^ o.y;
}

// Correctly-rounded fp32 divide, fast path only (valid: normal operands,
// no overflow/denormal — here den in [1, 3.3e5], inter in [0, 4.1e4]).
// Bit-identical to __fdiv_rn for these ranges.
__device__ __forceinline__ float fdiv_rn_fast(float a, float b) {
  float y;
  asm("rcp.approx.f32 %0, %1;" : "=f"(y) : "f"(b));
  float e = __fmaf_rn(-b, y, 1.0f);
  y = __fmaf_rn(e, y, y);
  float q = __fmul_rn(a, y);
  float r = __fmaf_rn(-b, q, a);
  return __fmaf_rn(r, y, q);
}

// ---------------------------------------------------------------------------
// Stage 1: per-proposal max IoU / argmax / label / r  (bit-exact)
// ---------------------------------------------------------------------------
__global__ void ptl_stage1(const float* __restrict__ prop, const float* __restrict__ gt) {
  __shared__ float4 sgt[GG];
  __shared__ float  sag[GG];
  const int b = blockIdx.y;
  const int n = blockIdx.x * blockDim.x + threadIdx.x;
  if (threadIdx.x < GG) {
    float4 q = reinterpret_cast<const float4*>(gt)[b * GG + threadIdx.x];
    sgt[threadIdx.x] = q;
    sag[threadIdx.x] = __fmul_rn(__fsub_rn(q.z, q.x), __fsub_rn(q.w, q.y));
  }
  __syncthreads();

  float4 p = reinterpret_cast<const float4*>(prop)[b * NN + n];
  float ap = __fmul_rn(__fsub_rn(p.z, p.x), __fsub_rn(p.w, p.y));
  float best = 0.0f;   // iou >= 0 always; first-max semantics preserved
  int bi = 0;
#pragma unroll 4
  for (int g = 0; g < GG; ++g) {
    float4 q = sgt[g];
    float ix1 = fmaxf(p.x, q.x);
    float iy1 = fmaxf(p.y, q.y);
    float ix2 = fminf(p.z, q.z);
    float iy2 = fminf(p.w, q.w);
    float iw = fmaxf(__fsub_rn(ix2, ix1), 0.0f);
    float ih = fmaxf(__fsub_rn(iy2, iy1), 0.0f);
    float inter = __fmul_rn(iw, ih);
    float den = fmaxf(__fsub_rn(__fadd_rn(ap, sag[g]), inter), 1e-8f);
    float iou = fdiv_rn_fast(inter, den);
    if (iou > best) { best = iou; bi = g; }
  }
  int lab = (best >= 0.5f) ? 1 : ((best < 0.1f) ? 0 : -1);

  const int i = b * NN + n;
  unsigned bits = jax_bits((unsigned)i);
  float u = __fsub_rn(__uint_as_float((bits >> 9) | 0x3F800000u), 1.0f);

  g_label[i]  = lab;
  g_argmax[i] = bi;
  g_r[i]      = u;
}

// ---------------------------------------------------------------------------
// Stage 2: one CTA per batch. Data in registers; 32-bit radix select (4 passes)
// per phase + exact ascending-index tie fill; rank-by-count ordering.
// ---------------------------------------------------------------------------
__global__ void __launch_bounds__(1024) ptl_stage2(const float* __restrict__ prop,
                                                   const float* __restrict__ gt,
                                                   float* __restrict__ out) {
  __shared__ int hist[256];
  __shared__ int s_target, s_digit, s_npos, s_cnt, s_eqCnt;
  __shared__ int eqList[EQCAP];
  __shared__ unsigned long long skey[NS];

  const int b = blockIdx.x;
  const int tid = threadIdx.x;

  unsigned keyR[16], keyB[16];
  unsigned posM = 0, negM = 0, selM = 0;

#pragma unroll
  for (int j = 0; j < 16; ++j) {
    int n = tid + j * 1024;
    int l = __ldg(&g_label[b * NN + n]);
    keyR[j] = __float_as_uint(__ldg(&g_r[b * NN + n]));
    posM |= (unsigned)(l == 1) << j;
    negM |= (unsigned)(l == 0) << j;
  }
  if (tid == 0) { s_npos = 0; s_cnt = 0; }
  __syncthreads();
  {
    int c = __popc(posM);
    for (int o = 16; o; o >>= 1) c += __shfl_down_sync(0xffffffffu, c, o);
    if ((tid & 31) == 0) atomicAdd(&s_npos, c);
  }
  __syncthreads();
  const int npos = s_npos;

  // =================== Phase A: pos_sel (top-64 positives by r) ============
  if (npos <= NFG) {
    selM = posM;
  } else {
    unsigned prefix = 0;
    if (tid == 0) s_target = NFG;
    __syncthreads();
    for (int byte = 3; byte >= 0; --byte) {
      if (tid < 256) hist[tid] = 0;
      __syncthreads();
#pragma unroll
      for (int j = 0; j < 16; ++j) {
        int bv = 256;
        if ((posM >> j) & 1) {
          unsigned k = keyR[j];
          bool ok = (byte == 3) || (((k ^ prefix) >> (8 * (byte + 1))) == 0u);
          if (ok) bv = (int)((k >> (8 * byte)) & 255u);
        }
        unsigned m = __match_any_sync(0xffffffffu, bv);
        if (bv < 256 && (tid & 31) == (__ffs(m) - 1)) atomicAdd(&hist[bv], __popc(m));
      }
      __syncthreads();
      if (tid < 32) {
        int base = tid * 8, c8[8], s0 = 0;
#pragma unroll
        for (int i = 0; i < 8; ++i) { c8[i] = hist[base + i]; s0 += c8[i]; }
        int suf = s0;
#pragma unroll
        for (int o = 1; o < 32; o <<= 1) {
          int v = __shfl_down_sync(0xffffffffu, suf, o);
          if (tid + o < 32) suf += v;
        }
        int tgt = s_target;
        __syncwarp();
        int cum = suf - s0;
#pragma unroll
        for (int i = 7; i >= 0; --i) {
          int c = c8[i];
          if (cum < tgt && cum + c >= tgt) { s_digit = base + i; s_target = tgt - cum; }
          cum += c;
        }
      }
      __syncthreads();
      prefix |= (unsigned)s_digit << (8 * byte);
    }
    const unsigned TA = prefix;
    const int tiesA = s_target;
    __syncthreads();
    if (tid == 0) s_eqCnt = 0;
    __syncthreads();
#pragma unroll
    for (int j = 0; j < 16; ++j) {
      if (((posM >> j) & 1) && keyR[j] == TA) {
        int p = atomicAdd(&s_eqCnt, 1);
        if (p < EQCAP) eqList[p] = tid + j * 1024;
      }
    }
    __syncthreads();
    int E = min(s_eqCnt, EQCAP);
#pragma unroll
    for (int j = 0; j < 16; ++j) {
      if ((posM >> j) & 1) {
        unsigned k = keyR[j];
        if (k > TA) selM |= 1u << j;
        else if (k == TA) {
          int n = tid + j * 1024, rk = 0;
          for (int i = 0; i < E; ++i) rk += (eqList[i] < n);
          if (rk < tiesA) selM |= 1u << j;
        }
      }
    }
  }
  __syncthreads();

  // =================== Phase B: top-256 by prio = cat + r ==================
#pragma unroll
  for (int j = 0; j < 16; ++j) {
    float r = __uint_as_float(keyR[j]);
    float cat = ((selM >> j) & 1) ? 3.0f
              : ((negM >> j) & 1) ? 2.0f
              : ((posM >> j) & 1) ? 1.0f : 0.0f;
    keyB[j] = __float_as_uint(__fadd_rn(cat, r));
  }
  if (tid == 0) s_target = NS;
  __syncthreads();
  unsigned prefixB = 0;
  for (int byte = 3; byte >= 0; --byte) {
    if (tid < 256) hist[tid] = 0;
    __syncthreads();
#pragma unroll
    for (int j = 0; j < 16; ++j) {
      unsigned k = keyB[j];
      bool ok = (byte == 3) || (((k ^ prefixB) >> (8 * (byte + 1))) == 0u);
      int bv = ok ? (int)((k >> (8 * byte)) & 255u) : 256;
      unsigned m = __match_any_sync(0xffffffffu, bv);
      if (bv < 256 && (tid & 31) == (__ffs(m) - 1)) atomicAdd(&hist[bv], __popc(m));
    }
    __syncthreads();
    if (tid < 32) {
      int base = tid * 8, c8[8], s0 = 0;
#pragma unroll
      for (int i = 0; i < 8; ++i) { c8[i] = hist[base + i]; s0 += c8[i]; }
      int suf = s0;
#pragma unroll
      for (int o = 1; o < 32; o <<= 1) {
        int v = __shfl_down_sync(0xffffffffu, suf, o);
        if (tid + o < 32) suf += v;
      }
      int tgt = s_target;
      __syncwarp();
      int cum = suf - s0;
#pragma unroll
      for (int i = 7; i >= 0; --i) {
        int c = c8[i];
        if (cum < tgt && cum + c >= tgt) { s_digit = base + i; s_target = tgt - cum; }
        cum += c;
      }
    }
    __syncthreads();
    prefixB |= (unsigned)s_digit << (8 * byte);
  }
  const unsigned TB = prefixB;
  const int tiesB = s_target;
  __syncthreads();
  if (tid == 0) s_eqCnt = 0;
  if (tid < NS) skey[tid] = 0ull;
  __syncthreads();
#pragma unroll
  for (int j = 0; j < 16; ++j) {
    if (keyB[j] == TB) {
      int p = atomicAdd(&s_eqCnt, 1);
      if (p < EQCAP) eqList[p] = tid + j * 1024;
    }
  }
  __syncthreads();
  int E = min(s_eqCnt, EQCAP);
#pragma unroll
  for (int j = 0; j < 16; ++j) {
    unsigned k = keyB[j];
    int n = tid + j * 1024;
    bool acc = (k > TB);
    if (!acc && k == TB) {
      int rk = 0;
      for (int i = 0; i < E; ++i) rk += (eqList[i] < n);
      acc = (rk < tiesB);
    }
    if (acc) {
      int p = atomicAdd(&s_cnt, 1);
      if (p < NS)
        skey[p] = (((unsigned long long)k) << 32) | (unsigned)(NN - 1 - n);
    }
  }
  __syncthreads();

  // ---- rank-by-count ordering (keys distinct) + outputs ----
  if (tid < NS) {
    unsigned long long k = skey[tid];
    int rank = 0;
#pragma unroll 8
    for (int i = 0; i < NS; ++i) rank += (skey[i] > k);
    const int s = rank;

    int n = (NN - 1) - (int)(unsigned)(k & 0xFFFFFFFFull);
    int l = g_label[b * NN + n];
    int bl = (l == 1) ? 1 : 0;
    float4 p = reinterpret_cast<const float4*>(prop)[b * NN + n];
    int gi = g_argmax[b * NN + n];
    float4 q = reinterpret_cast<const float4*>(gt)[b * GG + gi];

    float rcx = __fmul_rn(__fadd_rn(p.x, p.z), 0.5f);
    float rcy = __fmul_rn(__fadd_rn(p.y, p.w), 0.5f);
    float rw  = __fsub_rn(p.z, p.x);
    float rh  = __fsub_rn(p.w, p.y);
    float gcx = __fmul_rn(__fadd_rn(q.x, q.z), 0.5f);
    float gcy = __fmul_rn(__fadd_rn(q.y, q.w), 0.5f);
    float gw  = __fsub_rn(q.z, q.x);
    float gh  = __fsub_rn(q.w, q.y);
    float dx = __fdiv_rn(__fsub_rn(gcx, rcx), rw);
    float dy = __fdiv_rn(__fsub_rn(gcy, rcy), rh);
    float dw = logf(__fdiv_rn(gw, rw));
    float dh = logf(__fdiv_rn(gh, rh));

    const int base = b * NS + s;
    float* roi  = out;                 // [16,256,4]
    float* labo = out + BB * NS * 4;   // [16,256]
    float* tgts = out + BB * NS * 5;   // [16,256,4]
    float* inw  = out + BB * NS * 9;   // [16,256,4]
    float* outw = out + BB * NS * 13;  // [16,256,4]

    roi[base * 4 + 0] = p.x; roi[base * 4 + 1] = p.y;
    roi[base * 4 + 2] = p.z; roi[base * 4 + 3] = p.w;
    labo[base] = (float)bl;
    tgts[base * 4 + 0] = dx; tgts[base * 4 + 1] = dy;
    tgts[base * 4 + 2] = dw; tgts[base * 4 + 3] = dh;
    float w = bl ? 1.0f : 0.0f;
    inw[base * 4 + 0] = w; inw[base * 4 + 1] = w;
    inw[base * 4 + 2] = w; inw[base * 4 + 3] = w;
    outw[base * 4 + 0] = w; outw[base * 4 + 1] = w;
    outw[base * 4 + 2] = w; outw[base * 4 + 3] = w;
  }
}

extern "C" void kernel_launch(void* const* d_in, const int* in_sizes, int n_in,
                              void* d_out, int out_size) {
  const float* prop = (const float*)d_in[0];  // (16,16384,4) f32
  const float* gt   = (const float*)d_in[1];  // (16,128,4)   f32
  float* out = (float*)d_out;

  ptl_stage1<<<dim3(NN / 256, BB), 256>>>(prop, gt);
  ptl_stage2<<<BB, 1024>>>(prop, gt, out);
}

// round 8
// speedup vs baseline: 3.2521x; 1.1140x over previous
#include <cuda_runtime.h>

#define BB 16
#define NN 16384
#define GG 128
#define NS 256
#define NFG 64
#define CAP 2048

typedef unsigned long long ull;

// Scratch (no allocations allowed).
__device__ unsigned g_packed[BB*NN];        // (m << 2) | labcode   (1=pos,2=neg,0=neu)
__device__ int      g_argmax[BB*NN];
__device__ int      g_hist[BB*3*2048];      // [b][cat(0=neu,1=pos,2=neg)][2048]; zeroed by stage2 each run

// ---------------------------------------------------------------------------
// JAX threefry2x32, key = jax.random.key(1) -> (0,1); partitionable path.
// ---------------------------------------------------------------------------
__device__ __forceinline__ uint2 threefry2x32(unsigned x0, unsigned x1) {
  const unsigned ks0 = 0u, ks1 = 1u, ks2 = 0x1BD11BDBu;
  unsigned ks[3] = {ks0, ks1, ks2};
  x0 += ks[0]; x1 += ks[1];
  const int R0[4] = {13, 15, 26, 6};
  const int R1[4] = {17, 29, 16, 24};
#pragma unroll
  for (int i = 0; i < 5; ++i) {
#pragma unroll
    for (int j = 0; j < 4; ++j) {
      int r = (i & 1) ? R1[j] : R0[j];
      x0 += x1;
      x1 = (x1 << r) | (x1 >> (32 - r));
      x1 ^= x0;
    }
    x0 += ks[(i + 1) % 3];
    x1 += ks[(i + 2) % 3] + (unsigned)(i + 1);
  }
  return make_uint2(x0, x1);
}
__device__ __forceinline__ unsigned jax_bits(unsigned i) {
  uint2 o = threefry2x32(0u, i);
  return o.x ^ o.y;
}

// Correctly-rounded fp32 divide, fast path only (operands normal, no overflow
// here: den in [1, 3.3e5], inter in [0, 4.1e4]). Bit-identical to __fdiv_rn.
__device__ __forceinline__ float fdiv_rn_fast(float a, float b) {
  float y;
  asm("rcp.approx.f32 %0, %1;" : "=f"(y) : "f"(b));
  float e = __fmaf_rn(-b, y, 1.0f);
  y = __fmaf_rn(e, y, y);
  float q = __fmul_rn(a, y);
  float r = __fmaf_rn(-b, q, a);
  return __fmaf_rn(r, y, q);
}

// ---------------------------------------------------------------------------
// Stage 1: IoU/label/argmax/m + per-batch m-histograms. 2 proposals/thread.
// ---------------------------------------------------------------------------
__device__ __forceinline__ void finish_el(int b, int n, float best, int bi) {
  int lc = (best >= 0.5f) ? 1 : ((best < 0.1f) ? 2 : 0);
  int i = b * NN + n;
  unsigned m = jax_bits((unsigned)i) >> 9;   // 23 bits; r = m * 2^-23 exactly
  g_packed[i] = (m << 2) | (unsigned)lc;
  g_argmax[i] = bi;
  atomicAdd(&g_hist[(b * 3 + lc) * 2048 + (int)(m >> 12)], 1);
}

__global__ void ptl_stage1(const float* __restrict__ prop, const float* __restrict__ gt) {
  __shared__ float4 sgt[GG];
  __shared__ float  sag[GG];
  const int b = blockIdx.y;
  const int tid = threadIdx.x;
  const int n0 = blockIdx.x * 512 + tid;       // handles n0 and n0+256
  if (tid < GG) {
    float4 q = reinterpret_cast<const float4*>(gt)[b * GG + tid];
    sgt[tid] = q;
    sag[tid] = __fmul_rn(__fsub_rn(q.z, q.x), __fsub_rn(q.w, q.y));
  }
  __syncthreads();

  float4 pA = reinterpret_cast<const float4*>(prop)[b * NN + n0];
  float4 pB = reinterpret_cast<const float4*>(prop)[b * NN + n0 + 256];
  float apA = __fmul_rn(__fsub_rn(pA.z, pA.x), __fsub_rn(pA.w, pA.y));
  float apB = __fmul_rn(__fsub_rn(pB.z, pB.x), __fsub_rn(pB.w, pB.y));
  float bestA = 0.0f, bestB = 0.0f;
  int biA = 0, biB = 0;
#pragma unroll 2
  for (int g = 0; g < GG; ++g) {
    float4 q = sgt[g];
    float ag = sag[g];
    {
      float ix1 = fmaxf(pA.x, q.x), iy1 = fmaxf(pA.y, q.y);
      float ix2 = fminf(pA.z, q.z), iy2 = fminf(pA.w, q.w);
      float iw = fmaxf(__fsub_rn(ix2, ix1), 0.0f);
      float ih = fmaxf(__fsub_rn(iy2, iy1), 0.0f);
      float inter = __fmul_rn(iw, ih);
      float den = fmaxf(__fsub_rn(__fadd_rn(apA, ag), inter), 1e-8f);
      float iou = fdiv_rn_fast(inter, den);
      if (iou > bestA) { bestA = iou; biA = g; }
    }
    {
      float ix1 = fmaxf(pB.x, q.x), iy1 = fmaxf(pB.y, q.y);
      float ix2 = fminf(pB.z, q.z), iy2 = fminf(pB.w, q.w);
      float iw = fmaxf(__fsub_rn(ix2, ix1), 0.0f);
      float ih = fmaxf(__fsub_rn(iy2, iy1), 0.0f);
      float inter = __fmul_rn(iw, ih);
      float den = fmaxf(__fsub_rn(__fadd_rn(apB, ag), inter), 1e-8f);
      float iou = fdiv_rn_fast(inter, den);
      if (iou > bestB) { bestB = iou; biB = g; }
    }
  }
  finish_el(b, n0, bestA, biA);
  finish_el(b, n0 + 256, bestB, biB);
}

// ---------------------------------------------------------------------------
// Stage 2 helpers
// ---------------------------------------------------------------------------
// Block-wide inclusive suffix sum over 1024 threads (thread t contributes v;
// returns sum over all t' >= t). wsum: 32-int smem scratch.
__device__ __forceinline__ int blockSuffixScan(int v, int* wsum) {
  __syncthreads();                         // protect wsum reuse across calls
  const int lane = threadIdx.x & 31, w = threadIdx.x >> 5;
  int s = v;
#pragma unroll
  for (int o = 1; o < 32; o <<= 1) {
    int x = __shfl_down_sync(0xffffffffu, s, o);
    if (lane + o < 32) s += x;
  }
  if (lane == 0) wsum[w] = s;              // warp total
  __syncthreads();
  if (threadIdx.x < 32) {
    int ws = wsum[threadIdx.x];
    int t2 = ws;
#pragma unroll
    for (int o = 1; o < 32; o <<= 1) {
      int x = __shfl_down_sync(0xffffffffu, t2, o);
      if (threadIdx.x + o < 32) t2 += x;
    }
    wsum[threadIdx.x] = t2 - ws;           // sum of warps strictly above
  }
  __syncthreads();
  return s + wsum[w];
}

// Find max bin B with suffix(B) >= T (thread t owns bins 2t,2t+1; sufT =
// suffix at bin 2t; h0,h1 = counts of bins 2t,2t+1). Requires 1 <= T <= total.
__device__ __forceinline__ int findCut(int sufT, int h0, int h1, int T, int* s_bin) {
  const int t = threadIdx.x;
  int s0 = sufT, s1 = sufT - h0, s2 = s1 - h1;
  if (s0 >= T && s1 < T) *s_bin = 2 * t;
  if (s1 >= T && s2 < T) *s_bin = 2 * t + 1;
  __syncthreads();
  int r = *s_bin;
  __syncthreads();
  return r;
}

// ---------------------------------------------------------------------------
// Stage 2: one CTA/batch. Histogram cuts -> single gather sweep -> exact
// ranking on ~300 candidates with rounded cat+r keys (bit-exact vs reference).
// ---------------------------------------------------------------------------
__global__ void __launch_bounds__(1024) ptl_stage2(const float* __restrict__ prop,
                                                   const float* __restrict__ gt,
                                                   float* __restrict__ out) {
  __shared__ int wsum[32];
  __shared__ int s_bin, s_tot, s_cnt;
  __shared__ ull candArr[CAP];
  __shared__ ull skey[CAP];

  const int b = blockIdx.x;
  const int tid = threadIdx.x;

  // Load per-batch histograms (thread t owns bins 2t,2t+1) and zero them for
  // the next replay (each location touched by exactly one thread).
  int2* hb = reinterpret_cast<int2*>(&g_hist[b * 3 * 2048]);
  int2 hU = hb[0 * 1024 + tid];
  int2 hP = hb[1 * 1024 + tid];
  int2 hN = hb[2 * 1024 + tid];
  hb[0 * 1024 + tid] = make_int2(0, 0);
  hb[1 * 1024 + tid] = make_int2(0, 0);
  hb[2 * 1024 + tid] = make_int2(0, 0);

  // positives
  int sufP = blockSuffixScan(hP.x + hP.y, wsum);
  if (tid == 0) s_tot = sufP;
  __syncthreads();
  const int npos = s_tot;
  int binA = 0;
  if (npos > NFG) binA = findCut(sufP, hP.x, hP.y, NFG, &s_bin);

  // negatives
  int sufN = blockSuffixScan(hN.x + hN.y, wsum);
  if (tid == 0) s_tot = sufN;
  __syncthreads();
  const int nneg = s_tot;
  const int S1 = (npos < NFG) ? npos : NFG;
  const int T2 = NS - S1;
  const bool fallback = (nneg < T2);
  int binB = 0;
  if (!fallback) binB = findCut(sufN, hN.x, hN.y, T2, &s_bin);

  unsigned mU = 0xFFFFFFFFu;                 // neutrals excluded unless fallback
  unsigned mA = (unsigned)binA << 12;
  unsigned mB = (unsigned)binB << 12;
  if (fallback) {
    mA = 0; mB = 0;
    int TU = T2 - nneg;                      // >= 1 in fallback
    int sufU = blockSuffixScan(hU.x + hU.y, wsum);
    int binU = findCut(sufU, hU.x, hU.y, TU, &s_bin);
    mU = (unsigned)binU << 12;
  }

  // ---- single gather sweep: candidate superset (cut bins fully included) ----
  if (tid == 0) s_cnt = 0;
  __syncthreads();
#pragma unroll
  for (int j = 0; j < 16; ++j) {
    int n = tid + j * 1024;
    unsigned pk = __ldg(&g_packed[b * NN + n]);
    unsigned lc = pk & 3u;
    unsigned m = pk >> 2;
    bool c = (lc == 1u) ? (npos <= NFG || m >= mA)
           : (lc == 2u) ? (m >= mB)
                        : (m >= mU);
    if (c) {
      int p = atomicAdd(&s_cnt, 1);
      if (p < CAP) candArr[p] = (((ull)m) << 16) | (((ull)lc) << 14) | (unsigned)n;
    }
  }
  __syncthreads();
  const int C = (s_cnt < CAP) ? s_cnt : CAP;

  // ---- exact keys: cat from exact top-NFG positive rank; prio = rn(cat+r) ----
  for (int i = tid; i < C; i += 1024) {
    ull rec = candArr[i];
    unsigned m = (unsigned)(rec >> 16);
    unsigned lc = (unsigned)(rec >> 14) & 3u;
    int n = (int)(rec & 0x3FFFull);
    float cat;
    if (lc == 1u) {
      bool sel = true;
      if (npos > NFG) {
        ull pkey = (((ull)m) << 14) | (unsigned)(NN - 1 - n);
        int rk = 0;
        for (int j = 0; j < C; ++j) {
          ull r2 = candArr[j];
          if ((((unsigned)(r2 >> 14)) & 3u) == 1u) {
            ull pk2 = ((r2 >> 16) << 14) | (unsigned)(NN - 1 - (int)(r2 & 0x3FFFull));
            rk += (pk2 > pkey);
          }
        }
        sel = (rk < NFG);                    // candidate-rank == global rank
      }
      cat = sel ? 3.0f : 1.0f;
    } else {
      cat = (lc == 2u) ? 2.0f : 0.0f;
    }
    float r = __fmul_rn((float)(int)m, 1.1920928955078125e-7f);  // m*2^-23 exact
    float prio = __fadd_rn(cat, r);
    skey[i] = (((ull)__float_as_uint(prio)) << 32) | (unsigned)(NN - 1 - n);
  }
  __syncthreads();

  // ---- rank-by-count (keys distinct); rank<256 == lax.top_k order ----
  for (int i = tid; i < C; i += 1024) {
    ull k = skey[i];
    int rank = 0;
    for (int j = 0; j < C; ++j) rank += (skey[j] > k);
    if (rank < NS) {
      ull rec = candArr[i];
      unsigned lc = (unsigned)(rec >> 14) & 3u;
      int n = (int)(rec & 0x3FFFull);
      int bl = (lc == 1u) ? 1 : 0;           // max(label,0)
      float4 p = reinterpret_cast<const float4*>(prop)[b * NN + n];
      int gi = g_argmax[b * NN + n];
      float4 q = reinterpret_cast<const float4*>(gt)[b * GG + gi];

      float rcx = __fmul_rn(__fadd_rn(p.x, p.z), 0.5f);
      float rcy = __fmul_rn(__fadd_rn(p.y, p.w), 0.5f);
      float rw  = __fsub_rn(p.z, p.x);
      float rh  = __fsub_rn(p.w, p.y);
      float gcx = __fmul_rn(__fadd_rn(q.x, q.z), 0.5f);
      float gcy = __fmul_rn(__fadd_rn(q.y, q.w), 0.5f);
      float gw  = __fsub_rn(q.z, q.x);
      float gh  = __fsub_rn(q.w, q.y);
      float dx = __fdiv_rn(__fsub_rn(gcx, rcx), rw);
      float dy = __fdiv_rn(__fsub_rn(gcy, rcy), rh);
      float dw = logf(__fdiv_rn(gw, rw));
      float dh = logf(__fdiv_rn(gh, rh));

      const int base = b * NS + rank;
      float* roi  = out;                 // [16,256,4]
      float* labo = out + BB * NS * 4;   // [16,256]
      float* tgts = out + BB * NS * 5;   // [16,256,4]
      float* inw  = out + BB * NS * 9;   // [16,256,4]
      float* outw = out + BB * NS * 13;  // [16,256,4]

      roi[base * 4 + 0] = p.x; roi[base * 4 + 1] = p.y;
      roi[base * 4 + 2] = p.z; roi[base * 4 + 3] = p.w;
      labo[base] = (float)bl;
      tgts[base * 4 + 0] = dx; tgts[base * 4 + 1] = dy;
      tgts[base * 4 + 2] = dw; tgts[base * 4 + 3] = dh;
      float w = bl ? 1.0f : 0.0f;
      inw[base * 4 + 0] = w; inw[base * 4 + 1] = w;
      inw[base * 4 + 2] = w; inw[base * 4 + 3] = w;
      outw[base * 4 + 0] = w; outw[base * 4 + 1] = w;
      outw[base * 4 + 2] = w; outw[base * 4 + 3] = w;
    }
  }
}

extern "C" void kernel_launch(void* const* d_in, const int* in_sizes, int n_in,
                              void* d_out, int out_size) {
  const float* prop = (const float*)d_in[0];  // (16,16384,4) f32
  const float* gt   = (const float*)d_in[1];  // (16,128,4)   f32
  float* out = (float*)d_out;

  ptl_stage1<<<dim3(NN / 512, BB), 256>>>(prop, gt);
  ptl_stage2<<<BB, 1024>>>(prop, gt, out);
}

// round 10
// speedup vs baseline: 3.4788x; 1.0697x over previous
#include <cuda_runtime.h>

#define BB 16
#define NN 16384
#define GG 128
#define NS 256
#define NFG 64
#define CAP 2048

typedef unsigned long long ull;

// Scratch (no allocations allowed).
__device__ __align__(16) unsigned g_packed[BB*NN];  // (m << 2) | labcode (1=pos,2=neg,0=neu)
__device__ int g_hist[BB*3*2048];                   // [b][cat(0=neu,1=pos,2=neg)][2048]; zeroed by stage2

// ---------------------------------------------------------------------------
// JAX threefry2x32, key = jax.random.key(1) -> (0,1); partitionable path.
// ---------------------------------------------------------------------------
__device__ __forceinline__ uint2 threefry2x32(unsigned x0, unsigned x1) {
  const unsigned ks0 = 0u, ks1 = 1u, ks2 = 0x1BD11BDBu;
  unsigned ks[3] = {ks0, ks1, ks2};
  x0 += ks[0]; x1 += ks[1];
  const int R0[4] = {13, 15, 26, 6};
  const int R1[4] = {17, 29, 16, 24};
#pragma unroll
  for (int i = 0; i < 5; ++i) {
#pragma unroll
    for (int j = 0; j < 4; ++j) {
      int r = (i & 1) ? R1[j] : R0[j];
      x0 += x1;
      x1 = (x1 << r) | (x1 >> (32 - r));
      x1 ^= x0;
    }
    x0 += ks[(i + 1) % 3];
    x1 += ks[(i + 2) % 3] + (unsigned)(i + 1);
  }
  return make_uint2(x0, x1);
}
__device__ __forceinline__ unsigned jax_bits(unsigned i) {
  uint2 o = threefry2x32(0u, i);
  return o.x ^ o.y;
}

// Correctly-rounded fp32 divide, fast path only (operands normal, no overflow
// here: den in [1, 3.3e5], inter in [0, 4.1e4]). Bit-identical to __fdiv_rn.
__device__ __forceinline__ float fdiv_rn_fast(float a, float b) {
  float y;
  asm("rcp.approx.f32 %0, %1;" : "=f"(y) : "f"(b));
  float e = __fmaf_rn(-b, y, 1.0f);
  y = __fmaf_rn(e, y, y);
  float q = __fmul_rn(a, y);
  float r = __fmaf_rn(-b, q, a);
  return __fmaf_rn(r, y, q);
}

__device__ __forceinline__ float iou_one(float4 p, float ap, float4 q, float ag) {
  float ix1 = fmaxf(p.x, q.x), iy1 = fmaxf(p.y, q.y);
  float ix2 = fminf(p.z, q.z), iy2 = fminf(p.w, q.w);
  float iw = fmaxf(__fsub_rn(ix2, ix1), 0.0f);
  float ih = fmaxf(__fsub_rn(iy2, iy1), 0.0f);
  float inter = __fmul_rn(iw, ih);
  // den = max(ap+ag-inter, 1e-8) : clamp provably no-op (den >= ag - ulp >= 0.99)
  float den = __fsub_rn(__fadd_rn(ap, ag), inter);
  return fdiv_rn_fast(inter, den);
}

// ---------------------------------------------------------------------------
// Stage 1: max-IoU label + m + per-batch m-histograms. 2 proposals/thread.
// (argmax deferred to stage2 for the 256 selected rows only)
// ---------------------------------------------------------------------------
__global__ void ptl_stage1(const float* __restrict__ prop, const float* __restrict__ gt) {
  __shared__ float4 sgt[GG];
  __shared__ float  sag[GG];
  const int b = blockIdx.y;
  const int tid = threadIdx.x;
  const int n0 = blockIdx.x * 512 + tid;       // handles n0 and n0+256
  if (tid < GG) {
    float4 q = reinterpret_cast<const float4*>(gt)[b * GG + tid];
    sgt[tid] = q;
    sag[tid] = __fmul_rn(__fsub_rn(q.z, q.x), __fsub_rn(q.w, q.y));
  }
  __syncthreads();

  float4 pA = reinterpret_cast<const float4*>(prop)[b * NN + n0];
  float4 pB = reinterpret_cast<const float4*>(prop)[b * NN + n0 + 256];
  float apA = __fmul_rn(__fsub_rn(pA.z, pA.x), __fsub_rn(pA.w, pA.y));
  float apB = __fmul_rn(__fsub_rn(pB.z, pB.x), __fsub_rn(pB.w, pB.y));
  float bestA = 0.0f, bestB = 0.0f;
#pragma unroll 4
  for (int g = 0; g < GG; ++g) {
    float4 q = sgt[g];
    float ag = sag[g];
    bestA = fmaxf(bestA, iou_one(pA, apA, q, ag));
    bestB = fmaxf(bestB, iou_one(pB, apB, q, ag));
  }
#pragma unroll
  for (int e = 0; e < 2; ++e) {
    float best = e ? bestB : bestA;
    int n = n0 + e * 256;
    int lc = (best >= 0.5f) ? 1 : ((best < 0.1f) ? 2 : 0);
    int i = b * NN + n;
    unsigned m = jax_bits((unsigned)i) >> 9;   // 23 bits; r = m * 2^-23 exactly
    g_packed[i] = (m << 2) | (unsigned)lc;
    atomicAdd(&g_hist[(b * 3 + lc) * 2048 + (int)(m >> 12)], 1);
  }
}

// ---------------------------------------------------------------------------
// Stage 2 helpers
// ---------------------------------------------------------------------------
// Block-wide inclusive suffix sum over 1024 threads, 3 channels at once.
__device__ __forceinline__ int3 blockSuffixScan3(int3 v, int3* wsum) {
  const int lane = threadIdx.x & 31, w = threadIdx.x >> 5;
  int a = v.x, b2 = v.y, c = v.z;
#pragma unroll
  for (int o = 1; o < 32; o <<= 1) {
    int xa = __shfl_down_sync(0xffffffffu, a, o);
    int xb = __shfl_down_sync(0xffffffffu, b2, o);
    int xc = __shfl_down_sync(0xffffffffu, c, o);
    if (lane + o < 32) { a += xa; b2 += xb; c += xc; }
  }
  if (lane == 0) wsum[w] = make_int3(a, b2, c);
  __syncthreads();
  if (threadIdx.x < 32) {
    int3 t = wsum[threadIdx.x];
    int ta = t.x, tb = t.y, tc = t.z;
#pragma unroll
    for (int o = 1; o < 32; o <<= 1) {
      int xa = __shfl_down_sync(0xffffffffu, ta, o);
      int xb = __shfl_down_sync(0xffffffffu, tb, o);
      int xc = __shfl_down_sync(0xffffffffu, tc, o);
      if (threadIdx.x + o < 32) { ta += xa; tb += xb; tc += xc; }
    }
    wsum[threadIdx.x] = make_int3(ta - t.x, tb - t.y, tc - t.z);
  }
  __syncthreads();
  int3 r = wsum[w];
  return make_int3(a + r.x, b2 + r.y, c + r.z);
}

// Mark cut bin: thread t owns bins 2t,2t+1; suf = suffix at 2t; h0,h1 counts.
// Writes max bin B with suffix(B) >= T (requires 1 <= T <= total).
__device__ __forceinline__ void markCut(int suf, int h0, int h1, int T, int* dst) {
  int s0 = suf, s1 = suf - h0, s2 = s1 - h1;
  if (s0 >= T && s1 < T) *dst = 2 * (int)threadIdx.x;
  if (s1 >= T && s2 < T) *dst = 2 * (int)threadIdx.x + 1;
}

// ---------------------------------------------------------------------------
// Stage 2: one CTA/batch. Histogram cuts -> single gather sweep -> exact
// ranking on ~300 candidates with rounded cat+r keys (bit-exact vs reference).
// ---------------------------------------------------------------------------
__global__ void __launch_bounds__(1024) ptl_stage2(const float* __restrict__ prop,
                                                   const float* __restrict__ gt,
                                                   float* __restrict__ out) {
  __shared__ int3 wsum[32];
  __shared__ int s_binP, s_binN, s_binU, s_cnt;
  __shared__ int3 s_tot;
  __shared__ float4 sgt[GG];
  __shared__ float  sag[GG];
  __shared__ ull candArr[CAP];
  __shared__ ull skey[CAP];

  const int b = blockIdx.x;
  const int tid = threadIdx.x;

  // Prefetch packed data early (hide latency under histogram phase).
  uint4 pk[4];
  const uint4* gp = reinterpret_cast<const uint4*>(&g_packed[b * NN]);
#pragma unroll
  for (int j = 0; j < 4; ++j) pk[j] = __ldg(&gp[tid + j * 1024]);

  // gt tile + areas into smem (used at the end for argmax recompute).
  if (tid < GG) {
    float4 q = reinterpret_cast<const float4*>(gt)[b * GG + tid];
    sgt[tid] = q;
    sag[tid] = __fmul_rn(__fsub_rn(q.z, q.x), __fsub_rn(q.w, q.y));
  }

  // Load per-batch histograms (thread t owns bins 2t,2t+1), zero for next replay.
  int2* hb = reinterpret_cast<int2*>(&g_hist[b * 3 * 2048]);
  int2 hU = hb[0 * 1024 + tid];
  int2 hP = hb[1 * 1024 + tid];
  int2 hN = hb[2 * 1024 + tid];
  hb[0 * 1024 + tid] = make_int2(0, 0);
  hb[1 * 1024 + tid] = make_int2(0, 0);
  hb[2 * 1024 + tid] = make_int2(0, 0);

  if (tid == 0) { s_cnt = 0; s_binP = 0; s_binN = 0; s_binU = 2048; }
  __syncthreads();

  int3 suf = blockSuffixScan3(make_int3(hP.x + hP.y, hN.x + hN.y, hU.x + hU.y), wsum);
  if (tid == 0) s_tot = suf;   // thread 0 suffix == grand totals
  __syncthreads();
  const int npos = s_tot.x, nneg = s_tot.y;
  const int S1 = (npos < NFG) ? npos : NFG;
  const int T2 = NS - S1;
  const bool fallback = (nneg < T2);
  const int TU = T2 - nneg - ((npos > NFG) ? (npos - NFG) : 0);

  if (npos > NFG && !fallback) markCut(suf.x, hP.x, hP.y, NFG, &s_binP);
  if (!fallback)               markCut(suf.y, hN.x, hN.y, T2,  &s_binN);
  else if (TU >= 1)            markCut(suf.z, hU.x, hU.y, TU,  &s_binU);
  __syncthreads();

  const unsigned mA = (npos > NFG && !fallback) ? ((unsigned)s_binP << 12) : 0u;
  const unsigned mB = fallback ? 0u : ((unsigned)s_binN << 12);
  const unsigned mU = (unsigned)s_binU << 12;   // 2048<<12 = 2^23 excludes all

  // ---- single gather sweep, warp-aggregated append ----
  const int lane = tid & 31;
#pragma unroll
  for (int j = 0; j < 4; ++j) {
    unsigned vals[4] = {pk[j].x, pk[j].y, pk[j].z, pk[j].w};
#pragma unroll
    for (int e = 0; e < 4; ++e) {
      int n = (tid + j * 1024) * 4 + e;
      unsigned v = vals[e];
      unsigned lc = v & 3u;
      unsigned m = v >> 2;
      bool c = (lc == 1u) ? (m >= mA) : (lc == 2u) ? (m >= mB) : (m >= mU);
      unsigned ball = __ballot_sync(0xffffffffu, c);
      if (ball) {
        int leader = __ffs(ball) - 1;
        int base;
        if (lane == leader) base = atomicAdd(&s_cnt, __popc(ball));
        base = __shfl_sync(0xffffffffu, base, leader);
        int off = base + __popc(ball & ((1u << lane) - 1u));
        if (c && off < CAP)
          candArr[off] = (((ull)m) << 16) | (((ull)lc) << 14) | (unsigned)n;
      }
    }
  }
  __syncthreads();
  const int C = (s_cnt < CAP) ? s_cnt : CAP;

  // ---- exact keys: cat from exact top-NFG positive rank; prio = rn(cat+r) ----
  for (int i = tid; i < C; i += 1024) {
    ull rec = candArr[i];
    unsigned m = (unsigned)(rec >> 16);
    unsigned lc = (unsigned)(rec >> 14) & 3u;
    int n = (int)(rec & 0x3FFFull);
    float cat;
    if (lc == 1u) {
      bool sel = true;
      if (npos > NFG) {
        ull pkey = (((ull)m) << 14) | (unsigned)(NN - 1 - n);
        int rk = 0;
        for (int j = 0; j < C; ++j) {
          ull r2 = candArr[j];
          if ((((unsigned)(r2 >> 14)) & 3u) == 1u) {
            ull pk2 = ((r2 >> 16) << 14) | (unsigned)(NN - 1 - (int)(r2 & 0x3FFFull));
            rk += (pk2 > pkey);
          }
        }
        sel = (rk < NFG);                    // candidate-rank == global rank
      }
      cat = sel ? 3.0f : 1.0f;
    } else {
      cat = (lc == 2u) ? 2.0f : 0.0f;
    }
    float r = __fmul_rn((float)(int)m, 1.1920928955078125e-7f);  // m*2^-23 exact
    float prio = __fadd_rn(cat, r);
    skey[i] = (((ull)__float_as_uint(prio)) << 32) | (unsigned)(NN - 1 - n);
  }
  __syncthreads();

  // ---- rank-by-count (keys distinct); rank<256 == lax.top_k order ----
  for (int i = tid; i < C; i += 1024) {
    ull k = skey[i];
    int rank = 0;
    for (int j = 0; j < C; ++j) rank += (skey[j] > k);
    if (rank < NS) {
      ull rec = candArr[i];
      unsigned lc = (unsigned)(rec >> 14) & 3u;
      int n = (int)(rec & 0x3FFFull);
      int bl = (lc == 1u) ? 1 : 0;           // max(label,0)
      float4 p = reinterpret_cast<const float4*>(prop)[b * NN + n];
      float ap = __fmul_rn(__fsub_rn(p.z, p.x), __fsub_rn(p.w, p.y));

      // exact first-max argmax over 128 gt (bit-identical to reference)
      float best = 0.0f;
      int gi = 0;
#pragma unroll 4
      for (int g = 0; g < GG; ++g) {
        float iou = iou_one(p, ap, sgt[g], sag[g]);
        if (iou > best) { best = iou; gi = g; }
      }
      float4 q = sgt[gi];

      float rcx = __fmul_rn(__fadd_rn(p.x, p.z), 0.5f);
      float rcy = __fmul_rn(__fadd_rn(p.y, p.w), 0.5f);
      float rw  = __fsub_rn(p.z, p.x);
      float rh  = __fsub_rn(p.w, p.y);
      float gcx = __fmul_rn(__fadd_rn(q.x, q.z), 0.5f);
      float gcy = __fmul_rn(__fadd_rn(q.y, q.w), 0.5f);
      float gw  = __fsub_rn(q.z, q.x);
      float gh  = __fsub_rn(q.w, q.y);
      float dx = __fdiv_rn(__fsub_rn(gcx, rcx), rw);
      float dy = __fdiv_rn(__fsub_rn(gcy, rcy), rh);
      float dw = logf(__fdiv_rn(gw, rw));
      float dh = logf(__fdiv_rn(gh, rh));

      const int base = b * NS + rank;
      float4* roi4  = reinterpret_cast<float4*>(out);
      float*  labo  = out + BB * NS * 4;
      float4* tgt4  = reinterpret_cast<float4*>(out + BB * NS * 5);
      float4* inw4  = reinterpret_cast<float4*>(out + BB * NS * 9);
      float4* outw4 = reinterpret_cast<float4*>(out + BB * NS * 13);

      float w = bl ? 1.0f : 0.0f;
      roi4[base]  = p;
      labo[base]  = (float)bl;
      tgt4[base]  = make_float4(dx, dy, dw, dh);
      inw4[base]  = make_float4(w, w, w, w);
      outw4[base] = make_float4(w, w, w, w);
    }
  }
}

extern "C" void kernel_launch(void* const* d_in, const int* in_sizes, int n_in,
                              void* d_out, int out_size) {
  const float* prop = (const float*)d_in[0];  // (16,16384,4) f32
  const float* gt   = (const float*)d_in[1];  // (16,128,4)   f32
  float* out = (float*)d_out;

  ptl_stage1<<<dim3(NN / 512, BB), 256>>>(prop, gt);
  ptl_stage2<<<BB, 1024>>>(prop, gt, out);
}

// round 11
// speedup vs baseline: 4.7330x; 1.3605x over previous
#include <cuda_runtime.h>

#define BB 16
#define NN 16384
#define GG 128
#define NS 256
#define NFG 64
#define CAP 2048

typedef unsigned long long ull;

// Scratch (no allocations allowed).
__device__ __align__(16) unsigned g_packed[BB*NN];  // (m << 2) | labcode (1=pos,2=neg,0=neu)
__device__ int g_hist[BB*3*2048];                   // [b][cat(0=neu,1=pos,2=neg)][2048]; zeroed by stage2

// ---------------------------------------------------------------------------
// JAX threefry2x32, key = jax.random.key(1) -> (0,1); partitionable path.
// ---------------------------------------------------------------------------
__device__ __forceinline__ uint2 threefry2x32(unsigned x0, unsigned x1) {
  const unsigned ks0 = 0u, ks1 = 1u, ks2 = 0x1BD11BDBu;
  unsigned ks[3] = {ks0, ks1, ks2};
  x0 += ks[0]; x1 += ks[1];
  const int R0[4] = {13, 15, 26, 6};
  const int R1[4] = {17, 29, 16, 24};
#pragma unroll
  for (int i = 0; i < 5; ++i) {
#pragma unroll
    for (int j = 0; j < 4; ++j) {
      int r = (i & 1) ? R1[j] : R0[j];
      x0 += x1;
      x1 = (x1 << r) | (x1 >> (32 - r));
      x1 ^= x0;
    }
    x0 += ks[(i + 1) % 3];
    x1 += ks[(i + 2) % 3] + (unsigned)(i + 1);
  }
  return make_uint2(x0, x1);
}
__device__ __forceinline__ unsigned jax_bits(unsigned i) {
  uint2 o = threefry2x32(0u, i);
  return o.x ^ o.y;
}

// Correctly-rounded fp32 divide, fast path only (operands normal, no overflow
// here). Bit-identical to __fdiv_rn for these ranges.
__device__ __forceinline__ float fdiv_rn_fast(float a, float b) {
  float y;
  asm("rcp.approx.f32 %0, %1;" : "=f"(y) : "f"(b));
  float e = __fmaf_rn(-b, y, 1.0f);
  y = __fmaf_rn(e, y, y);
  float q = __fmul_rn(a, y);
  float r = __fmaf_rn(-b, q, a);
  return __fmaf_rn(r, y, q);
}

__device__ __forceinline__ float iou_one(float4 p, float ap, float4 q, float ag) {
  float ix1 = fmaxf(p.x, q.x), iy1 = fmaxf(p.y, q.y);
  float ix2 = fminf(p.z, q.z), iy2 = fminf(p.w, q.w);
  float iw = fmaxf(__fsub_rn(ix2, ix1), 0.0f);
  float ih = fmaxf(__fsub_rn(iy2, iy1), 0.0f);
  float inter = __fmul_rn(iw, ih);
  // max(.,1e-8) clamp provably no-op: den >= ag - ulp >= 0.99
  float den = __fsub_rn(__fadd_rn(ap, ag), inter);
  return fdiv_rn_fast(inter, den);
}

// ---------------------------------------------------------------------------
// Stage 1: division-free threshold labels (+ rare exact repair), m, histograms.
// ---------------------------------------------------------------------------
__global__ void ptl_stage1(const float* __restrict__ prop, const float* __restrict__ gt) {
  __shared__ float4 sgt[GG];
  __shared__ float  sag[GG];
  const int b = blockIdx.y;
  const int tid = threadIdx.x;
  const int n0 = blockIdx.x * 512 + tid;
  if (tid < GG) {
    float4 q = reinterpret_cast<const float4*>(gt)[b * GG + tid];
    sgt[tid] = q;
    sag[tid] = __fmul_rn(__fsub_rn(q.z, q.x), __fsub_rn(q.w, q.y));
  }
  __syncthreads();

  float4 pA = reinterpret_cast<const float4*>(prop)[b * NN + n0];
  float4 pB = reinterpret_cast<const float4*>(prop)[b * NN + n0 + 256];
  float apA = __fmul_rn(__fsub_rn(pA.z, pA.x), __fsub_rn(pA.w, pA.y));
  float apB = __fmul_rn(__fsub_rn(pB.z, pB.x), __fsub_rn(pB.w, pB.y));
  float s1A = -3.4e38f, s2A = -3.4e38f, s1B = -3.4e38f, s2B = -3.4e38f;
#pragma unroll 4
  for (int g = 0; g < GG; ++g) {
    float4 q = sgt[g];
    float ag = sag[g];
    {
      float ix1 = fmaxf(pA.x, q.x), iy1 = fmaxf(pA.y, q.y);
      float ix2 = fminf(pA.z, q.z), iy2 = fminf(pA.w, q.w);
      float iw = fmaxf(__fsub_rn(ix2, ix1), 0.0f);
      float ih = fmaxf(__fsub_rn(iy2, iy1), 0.0f);
      float inter = __fmul_rn(iw, ih);
      float den = __fsub_rn(__fadd_rn(apA, ag), inter);
      s1A = fmaxf(s1A, __fmaf_rn(-0.5f, den, inter));
      s2A = fmaxf(s2A, __fmaf_rn(-0.1f, den, inter));
    }
    {
      float ix1 = fmaxf(pB.x, q.x), iy1 = fmaxf(pB.y, q.y);
      float ix2 = fminf(pB.z, q.z), iy2 = fminf(pB.w, q.w);
      float iw = fmaxf(__fsub_rn(ix2, ix1), 0.0f);
      float ih = fmaxf(__fsub_rn(iy2, iy1), 0.0f);
      float inter = __fmul_rn(iw, ih);
      float den = __fsub_rn(__fadd_rn(apB, ag), inter);
      s1B = fmaxf(s1B, __fmaf_rn(-0.5f, den, inter));
      s2B = fmaxf(s2B, __fmaf_rn(-0.1f, den, inter));
    }
  }
#pragma unroll
  for (int e = 0; e < 2; ++e) {
    float s1 = e ? s1B : s1A, s2 = e ? s2B : s2A;
    float4 p = e ? pB : pA;
    float ap = e ? apB : apA;
    int n = n0 + e * 256;
    int lc;
    // danger band covers the rn(q)>=thr inclusion slack (2^-26*den resp 2^-28*den)
    bool danger = (s1 < 0.0f && s1 > -0.01f) || (s2 < 0.0f && s2 > -0.004f);
    if (danger) {
      float best = 0.0f;
      for (int g = 0; g < GG; ++g)
        best = fmaxf(best, iou_one(p, ap, sgt[g], sag[g]));
      lc = (best >= 0.5f) ? 1 : ((best < 0.1f) ? 2 : 0);
    } else {
      lc = (s1 >= 0.0f) ? 1 : ((s2 < 0.0f) ? 2 : 0);
    }
    int i = b * NN + n;
    unsigned m = jax_bits((unsigned)i) >> 9;   // r = m * 2^-23 exactly
    g_packed[i] = (m << 2) | (unsigned)lc;
    atomicAdd(&g_hist[(b * 3 + lc) * 2048 + (int)(m >> 12)], 1);
  }
}

// ---------------------------------------------------------------------------
// Stage 2 helpers
// ---------------------------------------------------------------------------
__device__ __forceinline__ int3 blockSuffixScan3(int3 v, int3* wsum) {
  const int lane = threadIdx.x & 31, w = threadIdx.x >> 5;
  int a = v.x, b2 = v.y, c = v.z;
#pragma unroll
  for (int o = 1; o < 32; o <<= 1) {
    int xa = __shfl_down_sync(0xffffffffu, a, o);
    int xb = __shfl_down_sync(0xffffffffu, b2, o);
    int xc = __shfl_down_sync(0xffffffffu, c, o);
    if (lane + o < 32) { a += xa; b2 += xb; c += xc; }
  }
  if (lane == 0) wsum[w] = make_int3(a, b2, c);
  __syncthreads();
  if (threadIdx.x < 32) {
    int3 t = wsum[threadIdx.x];
    int ta = t.x, tb = t.y, tc = t.z;
#pragma unroll
    for (int o = 1; o < 32; o <<= 1) {
      int xa = __shfl_down_sync(0xffffffffu, ta, o);
      int xb = __shfl_down_sync(0xffffffffu, tb, o);
      int xc = __shfl_down_sync(0xffffffffu, tc, o);
      if (threadIdx.x + o < 32) { ta += xa; tb += xb; tc += xc; }
    }
    wsum[threadIdx.x] = make_int3(ta - t.x, tb - t.y, tc - t.z);
  }
  __syncthreads();
  int3 r = wsum[w];
  return make_int3(a + r.x, b2 + r.y, c + r.z);
}

__device__ __forceinline__ void markCut(int suf, int h0, int h1, int T, int* dst) {
  int s0 = suf, s1 = suf - h0, s2 = s1 - h1;
  if (s0 >= T && s1 < T) *dst = 2 * (int)threadIdx.x;
  if (s1 >= T && s2 < T) *dst = 2 * (int)threadIdx.x + 1;
}

// count elements of arr[0..len8) (mult of 8, 0-padded) strictly greater than k
__device__ __forceinline__ int countGreater8(const ull* arr, int len8, ull k) {
  int rk = 0;
  for (int j = 0; j < len8; j += 8) {
    ull a0 = arr[j], a1 = arr[j+1], a2 = arr[j+2], a3 = arr[j+3];
    ull a4 = arr[j+4], a5 = arr[j+5], a6 = arr[j+6], a7 = arr[j+7];
    rk += (int)(a0 > k) + (int)(a1 > k) + (int)(a2 > k) + (int)(a3 > k)
        + (int)(a4 > k) + (int)(a5 > k) + (int)(a6 > k) + (int)(a7 > k);
  }
  return rk;
}

// ---------------------------------------------------------------------------
// Stage 2: one CTA/batch. Histogram cuts -> gather -> exact ranking.
// ---------------------------------------------------------------------------
__global__ void __launch_bounds__(1024) ptl_stage2(const float* __restrict__ prop,
                                                   const float* __restrict__ gt,
                                                   float* __restrict__ out) {
  __shared__ int3 wsum[32];
  __shared__ int s_binP, s_binN, s_binU, s_cnt, s_pcnt;
  __shared__ int3 s_tot;
  __shared__ float4 sgt[GG];
  __shared__ float  sag[GG];
  __shared__ ull candArr[CAP];
  __shared__ ull posArr[CAP];
  __shared__ ull skey[CAP];

  const int b = blockIdx.x;
  const int tid = threadIdx.x;

  // Prefetch packed data early (hidden under histogram phase).
  uint4 pk[4];
  const uint4* gp = reinterpret_cast<const uint4*>(&g_packed[b * NN]);
#pragma unroll
  for (int j = 0; j < 4; ++j) pk[j] = __ldg(&gp[tid + j * 1024]);

  if (tid < GG) {
    float4 q = reinterpret_cast<const float4*>(gt)[b * GG + tid];
    sgt[tid] = q;
    sag[tid] = __fmul_rn(__fsub_rn(q.z, q.x), __fsub_rn(q.w, q.y));
  }

  // Per-batch histograms (thread t owns bins 2t,2t+1); zero for next replay.
  int2* hb = reinterpret_cast<int2*>(&g_hist[b * 3 * 2048]);
  int2 hU = hb[0 * 1024 + tid];
  int2 hP = hb[1 * 1024 + tid];
  int2 hN = hb[2 * 1024 + tid];
  hb[0 * 1024 + tid] = make_int2(0, 0);
  hb[1 * 1024 + tid] = make_int2(0, 0);
  hb[2 * 1024 + tid] = make_int2(0, 0);

  if (tid == 0) { s_cnt = 0; s_pcnt = 0; s_binP = 0; s_binN = 0; s_binU = 2048; }
  __syncthreads();

  int3 suf = blockSuffixScan3(make_int3(hP.x + hP.y, hN.x + hN.y, hU.x + hU.y), wsum);
  if (tid == 0) s_tot = suf;
  __syncthreads();
  const int npos = s_tot.x, nneg = s_tot.y;
  const int S1 = (npos < NFG) ? npos : NFG;
  const int T2 = NS - S1;
  const bool fallback = (nneg < T2);
  const int TU = T2 - nneg - ((npos > NFG) ? (npos - NFG) : 0);

  if (npos > NFG && !fallback) markCut(suf.x, hP.x, hP.y, NFG, &s_binP);
  if (!fallback)               markCut(suf.y, hN.x, hN.y, T2,  &s_binN);
  else if (TU >= 1)            markCut(suf.z, hU.x, hU.y, TU,  &s_binU);
  __syncthreads();

  const unsigned mA = (npos > NFG && !fallback) ? ((unsigned)s_binP << 12) : 0u;
  const unsigned mB = fallback ? 0u : ((unsigned)s_binN << 12);
  const unsigned mU = (unsigned)s_binU << 12;
  const bool needPosRank = (npos > NFG);

  // ---- gather sweep, warp-aggregated appends (cand + positive keys) ----
  const int lane = tid & 31;
#pragma unroll
  for (int j = 0; j < 4; ++j) {
    unsigned vals[4] = {pk[j].x, pk[j].y, pk[j].z, pk[j].w};
#pragma unroll
    for (int e = 0; e < 4; ++e) {
      int n = (tid + j * 1024) * 4 + e;
      unsigned v = vals[e];
      unsigned lc = v & 3u;
      unsigned m = v >> 2;
      bool c = (lc == 1u) ? (m >= mA) : (lc == 2u) ? (m >= mB) : (m >= mU);
      unsigned ball = __ballot_sync(0xffffffffu, c);
      if (ball) {
        int leader = __ffs(ball) - 1;
        int base;
        if (lane == leader) base = atomicAdd(&s_cnt, __popc(ball));
        base = __shfl_sync(0xffffffffu, base, leader);
        int off = base + __popc(ball & ((1u << lane) - 1u));
        if (c && off < CAP)
          candArr[off] = (((ull)m) << 16) | (((ull)lc) << 14) | (unsigned)n;
      }
      if (needPosRank) {
        bool cp = c && (lc == 1u);
        unsigned ballp = __ballot_sync(0xffffffffu, cp);
        if (ballp) {
          int leader = __ffs(ballp) - 1;
          int base;
          if (lane == leader) base = atomicAdd(&s_pcnt, __popc(ballp));
          base = __shfl_sync(0xffffffffu, base, leader);
          int off = base + __popc(ballp & ((1u << lane) - 1u));
          if (cp && off < CAP)
            posArr[off] = (((ull)m) << 14) | (unsigned)(NN - 1 - n);
        }
      }
    }
  }
  __syncthreads();
  const int C = (s_cnt < CAP) ? s_cnt : CAP;
  const int C8 = (C + 7) & ~7;
  const int P = (s_pcnt < CAP) ? s_pcnt : CAP;
  const int P8 = (P + 7) & ~7;

  // zero-pad posArr for the unrolled scan
  if (tid < P8 - P) posArr[P + tid] = 0ull;
  __syncthreads();

  // ---- exact keys: cat via exact top-NFG positive rank; prio = rn(cat+r) ----
  if (tid < C8 - C) skey[C + tid] = 0ull;       // pad for unrolled rank
  for (int i = tid; i < C; i += 1024) {
    ull rec = candArr[i];
    unsigned m = (unsigned)(rec >> 16);
    unsigned lc = (unsigned)(rec >> 14) & 3u;
    int n = (int)(rec & 0x3FFFull);
    float cat;
    if (lc == 1u) {
      bool sel = true;
      if (needPosRank) {
        ull pkey = (((ull)m) << 14) | (unsigned)(NN - 1 - n);
        sel = (countGreater8(posArr, P8, pkey) < NFG);   // cand-rank == global rank
      }
      cat = sel ? 3.0f : 1.0f;
    } else {
      cat = (lc == 2u) ? 2.0f : 0.0f;
    }
    float r = __fmul_rn((float)(int)m, 1.1920928955078125e-7f);  // m*2^-23 exact
    float prio = __fadd_rn(cat, r);
    skey[i] = (((ull)__float_as_uint(prio)) << 32) | (unsigned)(NN - 1 - n);
  }
  __syncthreads();

  // ---- rank-by-count (keys distinct); rank<256 == lax.top_k order ----
  for (int i = tid; i < C; i += 1024) {
    ull k = skey[i];
    int rank = countGreater8(skey, C8, k);
    if (rank < NS) {
      ull rec = candArr[i];
      unsigned lc = (unsigned)(rec >> 14) & 3u;
      int n = (int)(rec & 0x3FFFull);
      int bl = (lc == 1u) ? 1 : 0;
      float4 p = reinterpret_cast<const float4*>(prop)[b * NN + n];
      float ap = __fmul_rn(__fsub_rn(p.z, p.x), __fsub_rn(p.w, p.y));

      // exact first-max argmax over 128 gt (bit-identical to reference)
      float best = 0.0f;
      int gi = 0;
#pragma unroll 4
      for (int g = 0; g < GG; ++g) {
        float iou = iou_one(p, ap, sgt[g], sag[g]);
        if (iou > best) { best = iou; gi = g; }
      }
      float4 q = sgt[gi];

      float rcx = __fmul_rn(__fadd_rn(p.x, p.z), 0.5f);
      float rcy = __fmul_rn(__fadd_rn(p.y, p.w), 0.5f);
      float rw  = __fsub_rn(p.z, p.x);
      float rh  = __fsub_rn(p.w, p.y);
      float gcx = __fmul_rn(__fadd_rn(q.x, q.z), 0.5f);
      float gcy = __fmul_rn(__fadd_rn(q.y, q.w), 0.5f);
      float gw  = __fsub_rn(q.z, q.x);
      float gh  = __fsub_rn(q.w, q.y);
      float dx = __fdiv_rn(__fsub_rn(gcx, rcx), rw);
      float dy = __fdiv_rn(__fsub_rn(gcy, rcy), rh);
      float dw = logf(__fdiv_rn(gw, rw));
      float dh = logf(__fdiv_rn(gh, rh));

      const int base = b * NS + rank;
      float4* roi4  = reinterpret_cast<float4*>(out);
      float*  labo  = out + BB * NS * 4;
      float4* tgt4  = reinterpret_cast<float4*>(out + BB * NS * 5);
      float4* inw4  = reinterpret_cast<float4*>(out + BB * NS * 9);
      float4* outw4 = reinterpret_cast<float4*>(out + BB * NS * 13);

      float w = bl ? 1.0f : 0.0f;
      roi4[base]  = p;
      labo[base]  = (float)bl;
      tgt4[base]  = make_float4(dx, dy, dw, dh);
      inw4[base]  = make_float4(w, w, w, w);
      outw4[base] = make_float4(w, w, w, w);
    }
  }
}

extern "C" void kernel_launch(void* const* d_in, const int* in_sizes, int n_in,
                              void* d_out, int out_size) {
  const float* prop = (const float*)d_in[0];  // (16,16384,4) f32
  const float* gt   = (const float*)d_in[1];  // (16,128,4)   f32
  float* out = (float*)d_out;

  ptl_stage1<<<dim3(NN / 512, BB), 256>>>(prop, gt);
  ptl_stage2<<<BB, 1024>>>(prop, gt, out);
}